// round 1
// baseline (speedup 1.0000x reference)
#include <cuda_runtime.h>
#include <math.h>

#define BB    16
#define CIN   64
#define COUT  64
#define NN    16384
#define NF    8192      // complex FFT size (N/2)
#define MODES 2048
#define TEMB  512

// Skewed shared index: every 8 complexes insert 1 pad -> breaks the stride-64B
// STS bank conflicts of the low-Ns Stockham stages (16-way -> 2-way).
#define IDX(a) ((a) + ((a) >> 3))
#define SBUF   9216      // IDX(8191)=9214 < 9216

// ---------------- scratch (static device memory; no allocation) -------------
__device__ float2 g_Xm[BB * CIN * MODES];   // forward modes (+temb bias), 16MB
__device__ float2 g_Om[BB * COUT * MODES];  // contracted modes, 16MB
__device__ float  g_t [BB * CIN];           // temb bias per (b, c_in)
__device__ float2 g_W [NF];                 // e^{-2pi i u/8192}
__device__ float2 g_E [NF];                 // e^{-2pi i u/16384}

// ---------------- complex helpers -------------------------------------------
__device__ __forceinline__ float2 cmulf(float2 a, float2 b) {
    return make_float2(fmaf(a.x, b.x, -a.y * b.y), fmaf(a.x, b.y, a.y * b.x));
}
__device__ __forceinline__ float2 caddf(float2 a, float2 b) {
    return make_float2(a.x + b.x, a.y + b.y);
}
__device__ __forceinline__ float2 csubf(float2 a, float2 b) {
    return make_float2(a.x - b.x, a.y - b.y);
}

// DFT4 (forward, e^{-2pi i rk/4}), natural-order out
__device__ __forceinline__ void dft4(float2 a, float2 b, float2 c, float2 d, float2 y[4]) {
    float2 t0 = caddf(a, c), t1 = csubf(a, c);
    float2 t2 = caddf(b, d), t3 = csubf(b, d);
    y[0] = caddf(t0, t2);
    y[2] = csubf(t0, t2);
    y[1] = make_float2(t1.x + t3.y, t1.y - t3.x);   // t1 - i*t3
    y[3] = make_float2(t1.x - t3.y, t1.y + t3.x);   // t1 + i*t3
}

// DFT8 (forward), natural-order in/out
__device__ __forceinline__ void fft8(float2 v[8]) {
    const float c = 0.70710678118654752f;
    float2 e[4], o[4];
    dft4(v[0], v[2], v[4], v[6], e);
    dft4(v[1], v[3], v[5], v[7], o);
    float2 o0 = o[0];
    float2 o1 = make_float2(c * (o[1].x + o[1].y), c * (o[1].y - o[1].x)); // *(c,-c)
    float2 o2 = make_float2(o[2].y, -o[2].x);                             // *(-i)
    float2 o3 = make_float2(c * (o[3].y - o[3].x), -c * (o[3].x + o[3].y)); // *(-c,-c)
    v[0] = caddf(e[0], o0);  v[4] = csubf(e[0], o0);
    v[1] = caddf(e[1], o1);  v[5] = csubf(e[1], o1);
    v[2] = caddf(e[2], o2);  v[6] = csubf(e[2], o2);
    v[3] = caddf(e[3], o3);  v[7] = csubf(e[3], o3);
}

// 8192-point forward complex FFT, Stockham autosort: 4 radix-8 stages + 1 radix-2.
// 1024 threads. Input in SA (skewed layout), result in SB (skewed). Natural order.
__device__ void fft8192_fwd(float2* SA, float2* SB) {
    const int tid = threadIdx.x;
    float2* src = SA;
    float2* dst = SB;
#pragma unroll
    for (int s = 0; s < 4; s++) {
        const int Ns    = 1 << (3 * s);
        const int shift = 10 - 3 * s;
        const int j = tid;                // exactly N/8 = 1024 work items
        const int t = j & (Ns - 1);
        float2 v[8];
#pragma unroll
        for (int r = 0; r < 8; r++) v[r] = src[IDX(j + (r << 10))];
#pragma unroll
        for (int r = 1; r < 8; r++) v[r] = cmulf(v[r], g_W[(r * t) << shift]);
        fft8(v);
        const int base = ((j >> (3 * s)) << (3 * s + 3)) + t;  // (j/Ns)*8Ns + t
#pragma unroll
        for (int r = 0; r < 8; r++) dst[IDX(base + (r << (3 * s)))] = v[r];
        __syncthreads();
        float2* tmp = src; src = dst; dst = tmp;
    }
    // final radix-2 stage, Ns = 4096 (src holds data, result -> dst = SB)
#pragma unroll
    for (int k = 0; k < 4; k++) {
        const int j = tid + (k << 10);
        float2 a = src[IDX(j)];
        float2 b = cmulf(src[IDX(j + 4096)], g_W[j]);
        dst[IDX(j)]        = caddf(a, b);
        dst[IDX(j + 4096)] = csubf(a, b);
    }
    __syncthreads();
}

// ---------------- kernel: twiddle tables ------------------------------------
__global__ void k_init() {
    int u = blockIdx.x * 256 + threadIdx.x;
    if (u < NF) {
        double a1 = -2.0 * 3.14159265358979323846 * (double)u / 8192.0;
        g_W[u] = make_float2((float)cos(a1), (float)sin(a1));
        double a2 = -2.0 * 3.14159265358979323846 * (double)u / 16384.0;
        g_E[u] = make_float2((float)cos(a2), (float)sin(a2));
    }
}

// ---------------- kernel: temb bias t[b,c] ----------------------------------
__global__ void k_bias(const float* __restrict__ temb,
                       const float* __restrict__ dw,
                       const float* __restrict__ db) {
    __shared__ float s_act[TEMB];
    __shared__ float s_part[256];
    const int b = blockIdx.x;
    const int tid = threadIdx.x;
    for (int k = tid; k < TEMB; k += 256) {
        float v = temb[b * TEMB + k];
        s_act[k] = v / (1.0f + expf(-v));          // SiLU
    }
    __syncthreads();
    const int c = tid & 63;
    const int p = tid >> 6;                        // 4 partial chunks of 128
    float sum = 0.0f;
    const float* w = dw + (size_t)c * TEMB;
    for (int k = p * 128; k < (p + 1) * 128; k++) sum = fmaf(s_act[k], w[k], sum);
    s_part[p * 64 + c] = sum;
    __syncthreads();
    if (tid < 64) {
        g_t[b * 64 + tid] = s_part[tid] + s_part[64 + tid] + s_part[128 + tid]
                          + s_part[192 + tid] + db[tid];
    }
}

// ---------------- kernel: forward rFFT + mode extraction + bias -------------
__global__ void __launch_bounds__(1024, 1)
k_fwd(const float* __restrict__ x) {
    extern __shared__ float2 sm[];
    float2* SA = sm;
    float2* SB = sm + SBUF;
    const int row = blockIdx.x;                    // b*64 + c_in
    const float2* xr = (const float2*)x + (size_t)row * NF;
    for (int k = threadIdx.x; k < NF; k += 1024) SA[IDX(k)] = xr[k];
    __syncthreads();
    fft8192_fwd(SA, SB);
    const float tb = g_t[row];
    for (int m = threadIdx.x; m < MODES; m += 1024) {
        float2 Zm = SB[IDX(m)];
        float2 Zn = SB[IDX((NF - m) & (NF - 1))];
        float2 A  = make_float2(Zm.x + Zn.x, Zm.y - Zn.y);   // Z + conj(Zn)
        float2 Bc = make_float2(Zm.x - Zn.x, Zm.y + Zn.y);   // Z - conj(Zn)
        float2 C  = cmulf(g_E[m], Bc);
        // X = 0.5*A - 0.5*i*C ; add temb bias to real part
        g_Xm[(size_t)row * MODES + m] =
            make_float2(0.5f * (A.x + C.y) + tb, 0.5f * (A.y - C.x));
    }
}

// ---------------- kernel: mode contraction (bim,iom->bom) -------------------
// grid: 256 blocks (8 modes each); block: 256 threads = 64 o x 4 mode-pairs.
__global__ void __launch_bounds__(256, 2)
k_einsum(const float* __restrict__ wr, const float* __restrict__ wi) {
    extern __shared__ float4 Xs[];                 // [ (b*64+i)*4 + mg ] : 64KB
    const int m0  = blockIdx.x * 8;
    const int tid = threadIdx.x;
    for (int idx = tid; idx < BB * CIN * 4; idx += 256) {
        const int mg = idx & 3;
        const int bi = idx >> 2;
        Xs[idx] = *((const float4*)(g_Xm + (size_t)bi * MODES + m0) + mg);
    }
    __syncthreads();
    const int o  = tid >> 2;
    const int mg = tid & 3;
    const int m  = m0 + 2 * mg;
    float ar0[BB], ai0[BB], ar1[BB], ai1[BB];
#pragma unroll
    for (int b = 0; b < BB; b++) { ar0[b] = ai0[b] = ar1[b] = ai1[b] = 0.0f; }

    for (int i = 0; i < CIN; i++) {
        const float2 wrv = *(const float2*)(wr + ((size_t)i * COUT + o) * MODES + m);
        const float2 wiv = *(const float2*)(wi + ((size_t)i * COUT + o) * MODES + m);
#pragma unroll
        for (int b = 0; b < BB; b++) {
            const float4 xv = Xs[(b * CIN + i) * 4 + mg]; // (xr0,xi0,xr1,xi1)
            ar0[b] = fmaf(xv.x, wrv.x, fmaf(-xv.y, wiv.x, ar0[b]));
            ai0[b] = fmaf(xv.x, wiv.x, fmaf( xv.y, wrv.x, ai0[b]));
            ar1[b] = fmaf(xv.z, wrv.y, fmaf(-xv.w, wiv.y, ar1[b]));
            ai1[b] = fmaf(xv.z, wiv.y, fmaf( xv.w, wrv.y, ai1[b]));
        }
    }
#pragma unroll
    for (int b = 0; b < BB; b++) {
        *((float4*)(g_Om + ((size_t)(b * COUT + o)) * MODES + m)) =
            make_float4(ar0[b], ai0[b], ar1[b], ai1[b]);
    }
}

// ---------------- kernel: inverse rFFT --------------------------------------
__global__ void __launch_bounds__(1024, 1)
k_inv(float* __restrict__ out) {
    extern __shared__ float2 sm[];
    float2* SA = sm;
    float2* SB = sm + SBUF;
    const int row = blockIdx.x;                    // b*64 + c_out
    const float2* orow = g_Om + (size_t)row * MODES;
    for (int m = threadIdx.x; m < NF; m += 1024) {
        float2 Xm = make_float2(0.0f, 0.0f);
        float2 Cc = make_float2(0.0f, 0.0f);
        if (m < MODES) {
            Xm = orow[m];
            if (m == 0) Xm.y = 0.0f;               // irfft drops Im(X[0])
        }
        const int mr = NF - m;
        if (mr < MODES) {                          // m > 6144 (mr>=1 since m<8192)
            float2 q = orow[mr];
            Cc = make_float2(q.x, -q.y);           // conj(X[8192-m])
        }
        float2 Ze = make_float2(0.5f * (Xm.x + Cc.x), 0.5f * (Xm.y + Cc.y));
        float2 D  = make_float2(0.5f * (Xm.x - Cc.x), 0.5f * (Xm.y - Cc.y));
        float2 e  = g_E[m];
        float2 Zo = cmulf(make_float2(e.x, -e.y), D);  // e^{+2pi i m/16384} * D
        // Z = Ze + i*Zo ; store conj(Z) so the forward FFT computes the inverse
        SA[IDX(m)] = make_float2(Ze.x - Zo.y, -(Ze.y + Zo.x));
    }
    __syncthreads();
    fft8192_fwd(SA, SB);
    const float sc = 1.0f / 8192.0f;
    float2* outr = (float2*)out + (size_t)row * NF;
    for (int k = threadIdx.x; k < NF; k += 1024) {
        float2 r = SB[IDX(k)];
        outr[k] = make_float2(r.x * sc, -r.y * sc); // conj + 1/N
    }
}

// ---------------- launch ----------------------------------------------------
extern "C" void kernel_launch(void* const* d_in, const int* in_sizes, int n_in,
                              void* d_out, int out_size) {
    const float* x    = (const float*)d_in[0];
    const float* temb = (const float*)d_in[1];
    const float* wr   = (const float*)d_in[2];
    const float* wi   = (const float*)d_in[3];
    const float* dw   = (const float*)d_in[4];
    const float* db   = (const float*)d_in[5];
    float* out = (float*)d_out;

    cudaFuncSetAttribute(k_fwd,    cudaFuncAttributeMaxDynamicSharedMemorySize, 2 * SBUF * 8);
    cudaFuncSetAttribute(k_inv,    cudaFuncAttributeMaxDynamicSharedMemorySize, 2 * SBUF * 8);
    cudaFuncSetAttribute(k_einsum, cudaFuncAttributeMaxDynamicSharedMemorySize, 65536);

    k_init  <<<32, 256>>>();
    k_bias  <<<BB, 256>>>(temb, dw, db);
    k_fwd   <<<BB * CIN, 1024, 2 * SBUF * 8>>>(x);
    k_einsum<<<MODES / 8, 256, 65536>>>(wr, wi);
    k_inv   <<<BB * COUT, 1024, 2 * SBUF * 8>>>(out);
}

// round 2
// speedup vs baseline: 1.2128x; 1.2128x over previous
#include <cuda_runtime.h>
#include <math.h>

#define BB    16
#define CIN   64
#define COUT  64
#define NN    16384
#define NF    8192      // complex FFT size (N/2)
#define MODES 2048
#define TEMB  512

// Skewed shared index: every 8 complexes insert 1 pad -> breaks the stride-64B
// STS bank conflicts of the low-Ns Stockham stages.
#define IDX(a) ((a) + ((a) >> 3))
#define SBUF   9216      // IDX(8191)=9214 < 9216  -> 73728 bytes (single buffer)

// ---------------- scratch (static device memory; no allocation) -------------
__device__ float2 g_Xm[BB * CIN * MODES];   // forward modes (+temb bias)
__device__ float2 g_Om[BB * COUT * MODES];  // contracted modes
__device__ float  g_t [BB * CIN];           // temb bias per (b, c_in)
__device__ float2 g_W [NF];                 // e^{-2pi i u/8192}
__device__ float2 g_E [NF];                 // e^{-2pi i u/16384}

// ---------------- complex helpers -------------------------------------------
__device__ __forceinline__ float2 cmulf(float2 a, float2 b) {
    return make_float2(fmaf(a.x, b.x, -a.y * b.y), fmaf(a.x, b.y, a.y * b.x));
}
__device__ __forceinline__ float2 caddf(float2 a, float2 b) {
    return make_float2(a.x + b.x, a.y + b.y);
}
__device__ __forceinline__ float2 csubf(float2 a, float2 b) {
    return make_float2(a.x - b.x, a.y - b.y);
}

// DFT4 (forward, e^{-2pi i rk/4}), natural-order out
__device__ __forceinline__ void dft4(float2 a, float2 b, float2 c, float2 d, float2 y[4]) {
    float2 t0 = caddf(a, c), t1 = csubf(a, c);
    float2 t2 = caddf(b, d), t3 = csubf(b, d);
    y[0] = caddf(t0, t2);
    y[2] = csubf(t0, t2);
    y[1] = make_float2(t1.x + t3.y, t1.y - t3.x);   // t1 - i*t3
    y[3] = make_float2(t1.x - t3.y, t1.y + t3.x);   // t1 + i*t3
}

// DFT8 (forward), natural-order in/out
__device__ __forceinline__ void fft8(float2 v[8]) {
    const float c = 0.70710678118654752f;
    float2 e[4], o[4];
    dft4(v[0], v[2], v[4], v[6], e);
    dft4(v[1], v[3], v[5], v[7], o);
    float2 o0 = o[0];
    float2 o1 = make_float2(c * (o[1].x + o[1].y), c * (o[1].y - o[1].x)); // *(c,-c)
    float2 o2 = make_float2(o[2].y, -o[2].x);                             // *(-i)
    float2 o3 = make_float2(c * (o[3].y - o[3].x), -c * (o[3].x + o[3].y)); // *(-c,-c)
    v[0] = caddf(e[0], o0);  v[4] = csubf(e[0], o0);
    v[1] = caddf(e[1], o1);  v[5] = csubf(e[1], o1);
    v[2] = caddf(e[2], o2);  v[6] = csubf(e[2], o2);
    v[3] = caddf(e[3], o3);  v[7] = csubf(e[3], o3);
}

// 8192-point forward complex FFT, Stockham autosort, SINGLE shared buffer.
// 512 threads, each owns 2 butterflies per stage (registers bridge the
// read->write barrier). 4 radix-8 stages + 1 radix-2.
// ZIN:   stage-0 inputs at r=2..5 are known-zero (inverse path) -> skip loads.
// PRUNE: final radix-2 stores only outputs in [0,2048) u (6144,8192) (fwd path).
template<bool ZIN, bool PRUNE>
__device__ void fft8192_sb(float2* S) {
    const int tid = threadIdx.x;              // 0..511
#pragma unroll
    for (int s = 0; s < 4; s++) {
        const int Ns    = 1 << (3 * s);
        const int shift = 10 - 3 * s;
        float2 v[2][8];
        int base[2];
#pragma unroll
        for (int h = 0; h < 2; h++) {
            const int j = tid + (h << 9);
            const int t = j & (Ns - 1);
#pragma unroll
            for (int r = 0; r < 8; r++) {
                if (ZIN && s == 0 && r >= 2 && r <= 5)
                    v[h][r] = make_float2(0.0f, 0.0f);
                else
                    v[h][r] = S[IDX(j + (r << 10))];
            }
#pragma unroll
            for (int r = 1; r < 8; r++) {
                if (!(ZIN && s == 0 && r >= 2 && r <= 5))
                    v[h][r] = cmulf(v[h][r], g_W[(r * t) << shift]);
            }
            fft8(v[h]);
            base[h] = ((j >> (3 * s)) << (3 * s + 3)) + t;  // (j/Ns)*8Ns + t
        }
        __syncthreads();
#pragma unroll
        for (int h = 0; h < 2; h++)
#pragma unroll
            for (int r = 0; r < 8; r++)
                S[IDX(base[h] + (r << (3 * s)))] = v[h][r];
        __syncthreads();
    }
    // final radix-2 stage, Ns = 4096: 8 pairs per thread
    float2 pa[8], pb[8];
#pragma unroll
    for (int k = 0; k < 8; k++) {
        const int j = tid + (k << 9);
        pa[k] = S[IDX(j)];
        pb[k] = cmulf(S[IDX(j + 4096)], g_W[j]);
    }
    __syncthreads();
#pragma unroll
    for (int k = 0; k < 8; k++) {
        const int j = tid + (k << 9);
        if (!PRUNE || j < 2048) S[IDX(j)]        = caddf(pa[k], pb[k]);
        if (!PRUNE || j > 2048) S[IDX(j + 4096)] = csubf(pa[k], pb[k]);
    }
    __syncthreads();
}

// ---------------- kernel: twiddle tables ------------------------------------
__global__ void k_init() {
    int u = blockIdx.x * 256 + threadIdx.x;
    if (u < NF) {
        double a1 = -2.0 * 3.14159265358979323846 * (double)u / 8192.0;
        g_W[u] = make_float2((float)cos(a1), (float)sin(a1));
        double a2 = -2.0 * 3.14159265358979323846 * (double)u / 16384.0;
        g_E[u] = make_float2((float)cos(a2), (float)sin(a2));
    }
}

// ---------------- kernel: temb bias t[b,c] ----------------------------------
__global__ void k_bias(const float* __restrict__ temb,
                       const float* __restrict__ dw,
                       const float* __restrict__ db) {
    __shared__ float s_act[TEMB];
    __shared__ float s_part[256];
    const int b = blockIdx.x;
    const int tid = threadIdx.x;
    for (int k = tid; k < TEMB; k += 256) {
        float v = temb[b * TEMB + k];
        s_act[k] = v / (1.0f + expf(-v));          // SiLU
    }
    __syncthreads();
    const int c = tid & 63;
    const int p = tid >> 6;                        // 4 partial chunks of 128
    float sum = 0.0f;
    const float* w = dw + (size_t)c * TEMB;
    for (int k = p * 128; k < (p + 1) * 128; k++) sum = fmaf(s_act[k], w[k], sum);
    s_part[p * 64 + c] = sum;
    __syncthreads();
    if (tid < 64) {
        g_t[b * 64 + tid] = s_part[tid] + s_part[64 + tid] + s_part[128 + tid]
                          + s_part[192 + tid] + db[tid];
    }
}

// ---------------- kernel: forward rFFT + mode extraction + bias -------------
__global__ void __launch_bounds__(512, 2)
k_fwd(const float* __restrict__ x) {
    extern __shared__ float2 sm[];
    float2* S = sm;
    const int row = blockIdx.x;                    // b*64 + c_in
    const float2* xr = (const float2*)x + (size_t)row * NF;
    for (int k = threadIdx.x; k < NF; k += 512) S[IDX(k)] = xr[k];
    __syncthreads();
    fft8192_sb<false, true>(S);
    const float tb = g_t[row];
    for (int m = threadIdx.x; m < MODES; m += 512) {
        float2 Zm = S[IDX(m)];
        float2 Zn = S[IDX((NF - m) & (NF - 1))];
        float2 A  = make_float2(Zm.x + Zn.x, Zm.y - Zn.y);   // Z + conj(Zn)
        float2 Bc = make_float2(Zm.x - Zn.x, Zm.y + Zn.y);   // Z - conj(Zn)
        float2 C  = cmulf(g_E[m], Bc);
        // X = 0.5*A - 0.5*i*C ; add temb bias to real part
        g_Xm[(size_t)row * MODES + m] =
            make_float2(0.5f * (A.x + C.y) + tb, 0.5f * (A.y - C.x));
    }
}

// ---------------- kernel: mode contraction (bim,iom->bom) -------------------
// grid: 256 blocks (8 modes each); block: 512 threads = 2 b-halves x 64 o x 4
// mode-pairs. 8 batch accumulators per thread (32 regs) -> high occupancy.
__global__ void __launch_bounds__(512, 2)
k_einsum(const float* __restrict__ wr, const float* __restrict__ wi) {
    extern __shared__ float4 Xs[];                 // [ (b*64+i)*4 + mg ] : 64KB
    const int m0  = blockIdx.x * 8;
    const int tid = threadIdx.x;
    for (int idx = tid; idx < BB * CIN * 4; idx += 512) {
        const int mg = idx & 3;
        const int bi = idx >> 2;
        Xs[idx] = *((const float4*)(g_Xm + (size_t)bi * MODES + m0) + mg);
    }
    __syncthreads();
    const int bh = tid >> 8;                       // batch half
    const int o  = (tid & 255) >> 2;
    const int mg = tid & 3;
    const int m  = m0 + 2 * mg;
    const int b0 = bh * 8;
    float ar0[8], ai0[8], ar1[8], ai1[8];
#pragma unroll
    for (int b = 0; b < 8; b++) { ar0[b] = ai0[b] = ar1[b] = ai1[b] = 0.0f; }

    for (int i = 0; i < CIN; i++) {
        const float2 wrv = *(const float2*)(wr + ((size_t)i * COUT + o) * MODES + m);
        const float2 wiv = *(const float2*)(wi + ((size_t)i * COUT + o) * MODES + m);
#pragma unroll
        for (int b = 0; b < 8; b++) {
            const float4 xv = Xs[((b0 + b) * CIN + i) * 4 + mg]; // (xr0,xi0,xr1,xi1)
            ar0[b] = fmaf(xv.x, wrv.x, fmaf(-xv.y, wiv.x, ar0[b]));
            ai0[b] = fmaf(xv.x, wiv.x, fmaf( xv.y, wrv.x, ai0[b]));
            ar1[b] = fmaf(xv.z, wrv.y, fmaf(-xv.w, wiv.y, ar1[b]));
            ai1[b] = fmaf(xv.z, wiv.y, fmaf( xv.w, wrv.y, ai1[b]));
        }
    }
#pragma unroll
    for (int b = 0; b < 8; b++) {
        *((float4*)(g_Om + ((size_t)((b0 + b) * COUT + o)) * MODES + m)) =
            make_float4(ar0[b], ai0[b], ar1[b], ai1[b]);
    }
}

// ---------------- kernel: inverse rFFT --------------------------------------
__global__ void __launch_bounds__(512, 2)
k_inv(float* __restrict__ out) {
    extern __shared__ float2 sm[];
    float2* S = sm;
    const int row = blockIdx.x;                    // b*64 + c_out
    const float2* orow = g_Om + (size_t)row * MODES;
    for (int m = threadIdx.x; m < NF; m += 512) {
        if (m >= MODES && m < NF - MODES) continue;  // stage-0 never reads these
        float2 Xm = make_float2(0.0f, 0.0f);
        float2 Cc = make_float2(0.0f, 0.0f);
        if (m < MODES) {
            Xm = orow[m];
            if (m == 0) Xm.y = 0.0f;               // irfft drops Im(X[0])
        }
        const int mr = NF - m;
        if (mr < MODES) {                          // m > 6144
            float2 q = orow[mr];
            Cc = make_float2(q.x, -q.y);           // conj(X[8192-m])
        }
        float2 Ze = make_float2(0.5f * (Xm.x + Cc.x), 0.5f * (Xm.y + Cc.y));
        float2 D  = make_float2(0.5f * (Xm.x - Cc.x), 0.5f * (Xm.y - Cc.y));
        float2 e  = g_E[m];
        float2 Zo = cmulf(make_float2(e.x, -e.y), D);  // e^{+2pi i m/16384} * D
        // Z = Ze + i*Zo ; store conj(Z) so the forward FFT computes the inverse
        S[IDX(m)] = make_float2(Ze.x - Zo.y, -(Ze.y + Zo.x));
    }
    __syncthreads();
    fft8192_sb<true, false>(S);
    const float sc = 1.0f / 8192.0f;
    float2* outr = (float2*)out + (size_t)row * NF;
    for (int k = threadIdx.x; k < NF; k += 512) {
        float2 r = S[IDX(k)];
        outr[k] = make_float2(r.x * sc, -r.y * sc); // conj + 1/N
    }
}

// ---------------- launch ----------------------------------------------------
extern "C" void kernel_launch(void* const* d_in, const int* in_sizes, int n_in,
                              void* d_out, int out_size) {
    const float* x    = (const float*)d_in[0];
    const float* temb = (const float*)d_in[1];
    const float* wr   = (const float*)d_in[2];
    const float* wi   = (const float*)d_in[3];
    const float* dw   = (const float*)d_in[4];
    const float* db   = (const float*)d_in[5];
    float* out = (float*)d_out;

    cudaFuncSetAttribute(k_fwd,    cudaFuncAttributeMaxDynamicSharedMemorySize, SBUF * 8);
    cudaFuncSetAttribute(k_inv,    cudaFuncAttributeMaxDynamicSharedMemorySize, SBUF * 8);
    cudaFuncSetAttribute(k_einsum, cudaFuncAttributeMaxDynamicSharedMemorySize, 65536);

    k_init  <<<32, 256>>>();
    k_bias  <<<BB, 256>>>(temb, dw, db);
    k_fwd   <<<BB * CIN, 512, SBUF * 8>>>(x);
    k_einsum<<<MODES / 8, 512, 65536>>>(wr, wi);
    k_inv   <<<BB * COUT, 512, SBUF * 8>>>(out);
}